// round 10
// baseline (speedup 1.0000x reference)
#include <cuda_runtime.h>
#include <stdint.h>

// MultiLevelHybridHashEncoding — instant-NGP hash-grid encoding.
// R9 -> R10: perf is pinned at ~73 L1TEX misses/point (1 miss/cyc/SM wall),
// insensitive to occupancy/MLP. Attack the miss count + L1 pollution:
//  - no smem -> full 228KB L1D carveout; levels 0..2 (221.6KB) become
//    L1-resident via allocating __ldg.
//  - levels 3..15 gathers via __ldcg (L2-only, no L1 allocation) so the
//    2.3GB miss stream cannot evict the hot coarse tables.
//  - x loads via __ldcg (12MB stream, no L1 pollution), stores __stcs.
// Layout unchanged: 32 lanes = 1 point, lane pair = (level, x-half),
// pair-coalesced gathers, shfl pair-reduce, coalesced 128B warp stores.

#define NLEVELS 16

#define P1 2654435761u
#define P2 805459861u
#define HMASK 0x7FFFFu

struct Params {
    const float2* tab[NLEVELS];
};

__device__ __constant__ int c_res[NLEVELS] = {
    16, 20, 25, 32, 40, 50, 64, 80, 101, 128, 161, 203, 256, 322, 406, 512
};

__global__ void __launch_bounds__(256, 7)
hashenc_kernel(const float* __restrict__ x, Params p,
               float2* __restrict__ out, int B)
{
    const int tid = blockIdx.x * 256 + threadIdx.x;
    const int b = tid >> 5;                     // warp -> point
    if (b >= B) return;

    const int ox = threadIdx.x & 1;             // x-corner this lane owns
    const int l  = (threadIdx.x >> 1) & 15;     // level this lane pair owns

    const int   res      = c_res[l];
    const int   res2     = res * res;
    const float sc       = 0.5f * (float)res;
    const bool  use_hash = (l >= 8);
    const bool  l1_hot   = (l < 3);             // keep coarse tables in L1
    const float2* __restrict__ tab = p.tab[l];

    // All 32 lanes broadcast the same 12 B; L2-only (don't pollute L1D).
    const float px = __ldcg(x + 3 * b + 0);
    const float py = __ldcg(x + 3 * b + 1);
    const float pz = __ldcg(x + 3 * b + 2);

    // xp = (x + 1) * (res/2) - 0.5, exact f32 op order of the reference.
    const float xp = __fadd_rn(__fmul_rn(__fadd_rn(px, 1.0f), sc), -0.5f);
    const float yp = __fadd_rn(__fmul_rn(__fadd_rn(py, 1.0f), sc), -0.5f);
    const float zp = __fadd_rn(__fmul_rn(__fadd_rn(pz, 1.0f), sc), -0.5f);

    const float fx = floorf(xp), fy = floorf(yp), fz = floorf(zp);
    const int ix = (int)fx, iy = (int)fy, iz = (int)fz;
    const float tx = __fsub_rn(xp, fx);
    const float ty = __fsub_rn(yp, fy);
    const float tz = __fsub_rn(zp, fz);
    const float ux = __fsub_rn(1.0f, tx);
    const float uy = __fsub_rn(1.0f, ty);
    const float uz = __fsub_rn(1.0f, tz);

    // This lane's x-corner (shared by its 4 corners).
    const int   cx = ix + ox;
    const float wx = ox ? tx : ux;
    const bool  vx = ((unsigned)cx < (unsigned)res);

    // ---- 4 corners (oy,oz); paired lanes (ox=0/1) coalesce in L1TEX ----
    float    w[4];
    unsigned idx[4];
    #pragma unroll
    for (int cc = 0; cc < 4; ++cc) {
        const int oy = (cc >> 1) & 1, oz = cc & 1;
        const int cy = iy + oy, cz = iz + oz;
        const bool valid = vx & ((unsigned)cy < (unsigned)res)
                              & ((unsigned)cz < (unsigned)res);
        const float ww = __fmul_rn(__fmul_rn(wx, oy ? ty : uy), oz ? tz : uz);
        w[cc] = valid ? ww : 0.0f;

        const unsigned hidx = ((unsigned)cx ^ ((unsigned)cy * P1)
                                            ^ ((unsigned)cz * P2)) & HMASK;
        const unsigned didx = (unsigned)(cx + cy * res + cz * res2);
        const unsigned ii = use_hash ? hidx : didx;
        idx[cc] = valid ? ii : 0u;
    }

    // ---- batched 4-wide gather ----
    // levels 0..2: allocating loads (L1-resident, 221.6KB of 228KB carveout)
    // levels 3..15: L2-only loads (no L1 allocation -> no table thrash)
    float2 e[4];
    if (l1_hot) {
        #pragma unroll
        for (int cc = 0; cc < 4; ++cc) e[cc] = __ldg(&tab[idx[cc]]);
    } else {
        #pragma unroll
        for (int cc = 0; cc < 4; ++cc) e[cc] = __ldcg(&tab[idx[cc]]);
    }

    float a0 = 0.0f, a1 = 0.0f;
    #pragma unroll
    for (int cc = 0; cc < 4; ++cc) {
        a0 = fmaf(e[cc].x, w[cc], a0);
        a1 = fmaf(e[cc].y, w[cc], a1);
    }

    // Pair reduction: even lane accumulates the odd lane's 4 corners.
    a0 += __shfl_xor_sync(0xffffffffu, a0, 1);
    a1 += __shfl_xor_sync(0xffffffffu, a1, 1);

    if (ox == 0) {
        // 16 even lanes store 128 contiguous bytes per warp.
        __stcs(&out[(size_t)b * NLEVELS + l], make_float2(a0, a1));
    }
}

extern "C" void kernel_launch(void* const* d_in, const int* in_sizes, int n_in,
                              void* d_out, int out_size)
{
    const float* x = (const float*)d_in[0];
    Params p;
    #pragma unroll
    for (int l = 0; l < NLEVELS; ++l) {
        p.tab[l] = (const float2*)d_in[1 + l];
    }
    const int B = in_sizes[0] / 3;

    const long long total = (long long)B * 32;   // 1 thread per (point,level,half)
    const int blocks = (int)((total + 255) / 256);
    hashenc_kernel<<<blocks, 256>>>(x, p, (float2*)d_out, B);
}

// round 11
// speedup vs baseline: 2.8354x; 2.8354x over previous
#include <cuda_runtime.h>
#include <stdint.h>

// MultiLevelHybridHashEncoding — instant-NGP hash-grid encoding.
// R10 -> R11: R6/R10 DRAM blowups correlate with huge-grid + 32-reg cap,
// not with cache-op routing — so re-test pollution control inside the
// known-good persistent R7 config, changing ONLY cache operators:
//   - x loads + level>=3 gathers: __ldcg (L2-only, no L1 allocation)
//   - level 2 gathers: __ldg (125KB table becomes L1-resident in the
//     131KB carveout once the polluting streams stop allocating)
//   - levels 0..1: shared memory (unchanged), stores __stcs (unchanged)

#define NLEVELS 16
#define TPB 768

#define L0_N 4096    // 16^3
#define L1_N 8000    // 20^3
#define SMEM_BYTES ((L0_N + L1_N) * 8)   // 96768 B per CTA

#define P1 2654435761u
#define P2 805459861u
#define HMASK 0x7FFFFu

struct Params {
    const float2* tab[NLEVELS];
};

__device__ __constant__ int c_res[NLEVELS] = {
    16, 20, 25, 32, 40, 50, 64, 80, 101, 128, 161, 203, 256, 322, 406, 512
};

extern __shared__ float2 s_tab[];

__global__ void __launch_bounds__(TPB, 2)
hashenc_kernel(const float* __restrict__ x, Params p,
               float2* __restrict__ out, int B)
{
    // ---- cooperative smem fill: levels 0..1, coalesced ----
    {
        const float2* __restrict__ t0 = p.tab[0];
        const float2* __restrict__ t1 = p.tab[1];
        for (int i = threadIdx.x; i < L0_N; i += TPB) s_tab[i] = __ldg(t0 + i);
        for (int i = threadIdx.x; i < L1_N; i += TPB) s_tab[L0_N + i] = __ldg(t1 + i);
    }
    __syncthreads();

    // Thread = (point, level, x-half). 32 consecutive threads = 1 point.
    const int   ox       = threadIdx.x & 1;        // x-corner this lane owns
    const int   l        = (threadIdx.x >> 1) & 15;
    const int   res      = c_res[l];
    const int   res2     = res * res;
    const float sc       = 0.5f * (float)res;
    const bool  in_smem  = (l < 2);
    const bool  l1_hot   = (l == 2);               // keep level-2 table in L1
    const bool  use_hash = (l >= 8);
    const float2* __restrict__ gtab = p.tab[l];
    const float2* __restrict__ stab = s_tab + (l == 0 ? 0 : L0_N);

    const int total  = B * NLEVELS * 2;             // (point, level, half) items
    const int stride = gridDim.x * TPB;
    int tid = blockIdx.x * TPB + threadIdx.x;
    if (tid >= total) return;

    // Prologue: load first point (all 32 lanes broadcast the same 12 B).
    // L2-only: the x stream must not allocate (and thrash) L1D.
    float px, py, pz;
    {
        const int b = tid >> 5;
        px = __ldcg(x + 3 * b + 0);
        py = __ldcg(x + 3 * b + 1);
        pz = __ldcg(x + 3 * b + 2);
    }

    while (true) {
        // ---- prefetch next iteration's point ----
        const int tid_n = tid + stride;
        float nx = 0.f, ny = 0.f, nz = 0.f;
        if (tid_n < total) {
            const int bn = tid_n >> 5;
            nx = __ldcg(x + 3 * bn + 0);
            ny = __ldcg(x + 3 * bn + 1);
            nz = __ldcg(x + 3 * bn + 2);
        }

        const int b = tid >> 5;

        // xp = (x + 1) * (res/2) - 0.5, exact f32 op order of the reference.
        const float xp = __fadd_rn(__fmul_rn(__fadd_rn(px, 1.0f), sc), -0.5f);
        const float yp = __fadd_rn(__fmul_rn(__fadd_rn(py, 1.0f), sc), -0.5f);
        const float zp = __fadd_rn(__fmul_rn(__fadd_rn(pz, 1.0f), sc), -0.5f);

        const float fx = floorf(xp), fy = floorf(yp), fz = floorf(zp);
        const int ix = (int)fx, iy = (int)fy, iz = (int)fz;
        const float tx = __fsub_rn(xp, fx);
        const float ty = __fsub_rn(yp, fy);
        const float tz = __fsub_rn(zp, fz);
        const float ux = __fsub_rn(1.0f, tx);
        const float uy = __fsub_rn(1.0f, ty);
        const float uz = __fsub_rn(1.0f, tz);

        // This lane's x-corner (shared by its 4 corners).
        const int   cx = ix + ox;
        const float wx = ox ? tx : ux;
        const bool  vx = ((unsigned)cx < (unsigned)res);

        // ---- 4 corners (oy,oz); paired lanes (ox=0/1) coalesce in L1TEX ----
        float    w[4];
        unsigned idx[4];
        #pragma unroll
        for (int cc = 0; cc < 4; ++cc) {
            const int oy = (cc >> 1) & 1, oz = cc & 1;
            const int cy = iy + oy, cz = iz + oz;
            const bool valid = vx & ((unsigned)cy < (unsigned)res)
                                  & ((unsigned)cz < (unsigned)res);
            const float ww = __fmul_rn(__fmul_rn(wx, oy ? ty : uy), oz ? tz : uz);
            w[cc] = valid ? ww : 0.0f;

            const unsigned hidx = ((unsigned)cx ^ ((unsigned)cy * P1)
                                                ^ ((unsigned)cz * P2)) & HMASK;
            const unsigned didx = (unsigned)(cx + cy * res + cz * res2);
            const unsigned ii = use_hash ? hidx : didx;
            idx[cc] = valid ? ii : 0u;
        }

        // ---- batched 4-wide gather ----
        // l<2: smem. l==2: allocating load (L1-resident 125KB table).
        // l>=3: L2-only load (no L1 allocation -> no pollution).
        float2 e[4];
        if (in_smem) {
            #pragma unroll
            for (int cc = 0; cc < 4; ++cc) e[cc] = stab[idx[cc]];
        } else if (l1_hot) {
            #pragma unroll
            for (int cc = 0; cc < 4; ++cc) e[cc] = __ldg(&gtab[idx[cc]]);
        } else {
            #pragma unroll
            for (int cc = 0; cc < 4; ++cc) e[cc] = __ldcg(&gtab[idx[cc]]);
        }

        float a0 = 0.0f, a1 = 0.0f;
        #pragma unroll
        for (int cc = 0; cc < 4; ++cc) {
            a0 = fmaf(e[cc].x, w[cc], a0);
            a1 = fmaf(e[cc].y, w[cc], a1);
        }

        // Pair reduction: even lane accumulates the odd lane's 4 corners.
        a0 += __shfl_xor_sync(0xffffffffu, a0, 1);
        a1 += __shfl_xor_sync(0xffffffffu, a1, 1);

        if (ox == 0) {
            // 16 even lanes store 128 contiguous bytes per warp.
            __stcs(&out[(size_t)b * NLEVELS + l], make_float2(a0, a1));
        }

        if (tid_n >= total) break;
        tid = tid_n;
        px = nx; py = ny; pz = nz;
    }
}

extern "C" void kernel_launch(void* const* d_in, const int* in_sizes, int n_in,
                              void* d_out, int out_size)
{
    const float* x = (const float*)d_in[0];
    Params p;
    #pragma unroll
    for (int l = 0; l < NLEVELS; ++l) {
        p.tab[l] = (const float2*)d_in[1 + l];
    }
    const int B = in_sizes[0] / 3;

    cudaFuncSetAttribute(hashenc_kernel,
                         cudaFuncAttributeMaxDynamicSharedMemorySize, SMEM_BYTES);

    int sms = 148;
    cudaDeviceGetAttribute(&sms, cudaDevAttrMultiProcessorCount, 0);

    hashenc_kernel<<<2 * sms, TPB, SMEM_BYTES>>>(x, p, (float2*)d_out, B);
}